// round 1
// baseline (speedup 1.0000x reference)
#include <cuda_runtime.h>

#define EPS 1e-12f
#define TPB 256        // threads per block
#define PPB 1024       // points per block (PPB = 4*TPB)

__global__ __launch_bounds__(TPB) void blinn_phong_kernel(
    const float* __restrict__ in,   // [n, 3, 3]
    const float* __restrict__ kd,   // [3]
    const float* __restrict__ ks,   // [3]
    const float* __restrict__ pp,   // [1]
    float* __restrict__ out,        // [n, 3]
    int n)
{
    __shared__ float s_in[PPB * 9];    // 36 KB
    __shared__ float s_out[PPB * 3];   // 12 KB

    const int tid  = threadIdx.x;
    const int base = blockIdx.x * PPB;
    const int npts = min(PPB, n - base);

    // Broadcast material params (L1-cached, uniform across warp)
    const float kd0 = kd[0], kd1 = kd[1], kd2 = kd[2];
    const float ks0 = ks[0], ks1 = ks[1], ks2 = ks[2];
    const float p   = pp[0];

    // ---- Stage 1: coalesced global -> smem ----
    if (npts == PPB) {
        // fast path: 2304 float4 loads, fully coalesced, 16B aligned
        const float4* g4 = reinterpret_cast<const float4*>(in + (size_t)base * 9);
        float4* s4 = reinterpret_cast<float4*>(s_in);
        #pragma unroll
        for (int i = 0; i < (PPB * 9) / 4 / TPB; ++i)
            s4[tid + i * TPB] = g4[tid + i * TPB];
    } else {
        const int nflt = npts * 9;
        for (int i = tid; i < nflt; i += TPB)
            s_in[i] = in[(size_t)base * 9 + i];
    }
    __syncthreads();

    // ---- Stage 2: compute (stride-9 smem reads: coprime w/ 32 banks, conflict-free)
    #pragma unroll
    for (int k = 0; k < PPB / TPB; ++k) {
        const int pt = tid + k * TPB;
        if (pt < npts) {
            const float* q = s_in + pt * 9;
            float lx = q[0], ly = q[1], lz = q[2];
            float nx = q[3], ny = q[4], nz = q[5];
            float vx = q[6], vy = q[7], vz = q[8];

            // diffuse
            float ln = fmaxf(0.0f, lx * nx + ly * ny + lz * nz);

            // half vector (unnormalized) + norm
            float hx = lx + vx, hy = ly + vy, hz = lz + vz;
            float hh = hx * hx + hy * hy + hz * hz;
            float norm = fmaxf(sqrtf(hh), EPS);

            // nh = max(0, dot(n, h/norm)) == max(0, dot(n,h)) / norm  (norm > 0)
            float ndh = fmaxf(0.0f, nx * hx + ny * hy + nz * hz) / norm;

            // specular: nh^p  (__powf(0,p)=0 for p>0 — matches reference)
            float s = __powf(ndh, p);

            float* o = s_out + pt * 3;     // stride-3: conflict-free
            o[0] = ks0 * s + kd0 * ln;
            o[1] = ks1 * s + kd1 * ln;
            o[2] = ks2 * s + kd2 * ln;
        }
    }
    __syncthreads();

    // ---- Stage 3: coalesced smem -> global ----
    if (npts == PPB) {
        const float4* s4 = reinterpret_cast<const float4*>(s_out);
        float4* g4 = reinterpret_cast<float4*>(out + (size_t)base * 3);
        #pragma unroll
        for (int i = 0; i < (PPB * 3) / 4 / TPB; ++i)
            g4[tid + i * TPB] = s4[tid + i * TPB];
    } else {
        const int nflt = npts * 3;
        for (int i = tid; i < nflt; i += TPB)
            out[(size_t)base * 3 + i] = s_out[i];
    }
}

extern "C" void kernel_launch(void* const* d_in, const int* in_sizes, int n_in,
                              void* d_out, int out_size)
{
    const float* in = (const float*)d_in[0];   // [N,3,3]
    const float* kd = (const float*)d_in[1];   // [3]
    const float* ks = (const float*)d_in[2];   // [3]
    const float* p  = (const float*)d_in[3];   // [1]
    float* out = (float*)d_out;                // [N,3]

    const int n = in_sizes[0] / 9;
    const int grid = (n + PPB - 1) / PPB;
    blinn_phong_kernel<<<grid, TPB>>>(in, kd, ks, p, out, n);
}